// round 12
// baseline (speedup 1.0000x reference)
#include <cuda_runtime.h>
#include <cuda_fp16.h>
#include <cstdint>

#define OMEGA 30.0f
#define P_TOTAL 50177
#define BATCH 16
#define N_PTS 32768
#define TILES_PER_CTA 2
#define CTAS_Y 128            // 128 * 2 * 128 = 32768 points per batch

#define WS 144                // padded K stride (fp16 elems): conflict-free v2 LDS
#define MS (128 * WS)         // 18432 elems per matrix
#define MATB (MS * 2)         // 36864 bytes per matrix

// small params per batch: W0[384]@0 b0@384 b1@512 b2@640 b3@768 Wo@896 bo@1024
__device__ __align__(16) float g_h2[BATCH * 256];
__device__ __align__(16) float g_small[BATCH][1040];
// per batch: W1, W2, W3 fp16, [n][k-interleaved] with row stride WS
__device__ __align__(16) unsigned short g_wblk[BATCH][3 * MS];

#define SMEM_TOTAL (3 * MATB)              // 110592 -> 2 CTAs/SM

// ---------------------------------------------------------------------------
// helpers
// ---------------------------------------------------------------------------
__device__ __forceinline__ uint32_t smem_u32(const void* p) {
    uint32_t a;
    asm("{ .reg .u64 t; cvta.to.shared.u64 t, %1; cvt.u32.u64 %0, t; }"
        : "=r"(a) : "l"(p));
    return a;
}
__device__ __forceinline__ void lds64(uint32_t a, uint32_t& x, uint32_t& y) {
    asm volatile("ld.shared.v2.b32 {%0,%1}, [%2];" : "=r"(x), "=r"(y) : "r"(a));
}
// D += A @ B^T, m16n8k16 fp16, fp32 accum (baseline PTX, works on sm_100)
__device__ __forceinline__ void mma_fp16(float* d, const uint32_t* a,
                                         uint32_t b0, uint32_t b1) {
    asm volatile(
        "mma.sync.aligned.m16n8k16.row.col.f32.f16.f16.f32 "
        "{%0,%1,%2,%3}, {%4,%5,%6,%7}, {%8,%9}, {%0,%1,%2,%3};"
        : "+f"(d[0]), "+f"(d[1]), "+f"(d[2]), "+f"(d[3])
        : "r"(a[0]), "r"(a[1]), "r"(a[2]), "r"(a[3]), "r"(b0), "r"(b1));
}
// two fp32 -> packed fp16x2 (first value in low half)
__device__ __forceinline__ uint32_t cvt2h(float v0, float v1) {
    __half h0 = __float2half_rn(v0), h1 = __float2half_rn(v1);
    return (uint32_t)__half_as_ushort(h0) | ((uint32_t)__half_as_ushort(h1) << 16);
}

// ---------------------------------------------------------------------------
// K1: hypernet hidden chain, 1024 threads, 4 threads/neuron.
// float4 weight loads, fully unrolled -> all 16 LDG.128 in flight at once
// (one DRAM roundtrip instead of 8 serial batches).
// ---------------------------------------------------------------------------
__global__ void __launch_bounds__(1024) hyper_hidden_kernel(
    const float* __restrict__ t,
    const float* __restrict__ hW0, const float* __restrict__ hb0,
    const float* __restrict__ hW1, const float* __restrict__ hb1,
    const float* __restrict__ hW2, const float* __restrict__ hb2) {
    __shared__ float ts[8];
    __shared__ float h0[256];
    __shared__ float h1[256];
    int b = blockIdx.x;
    int tid = threadIdx.x;
    if (tid < 8) ts[tid] = t[b * 8 + tid];
    __syncthreads();

    if (tid < 256) {
        float acc = hb0[tid];
#pragma unroll
        for (int i = 0; i < 8; i++) acc += ts[i] * hW0[tid * 8 + i];
        h0[tid] = __sinf(OMEGA * acc);
    }
    __syncthreads();

    int n = tid >> 2, part = tid & 3;
    {
        const float4* w = reinterpret_cast<const float4*>(hW1 + n * 256 + part * 64);
        const float4* h = reinterpret_cast<const float4*>(h0 + part * 64);
        float acc = 0.f;
#pragma unroll
        for (int i = 0; i < 16; i++) {
            float4 a = w[i], v = h[i];
            acc += a.x * v.x + a.y * v.y + a.z * v.z + a.w * v.w;
        }
        acc += __shfl_xor_sync(0xffffffffu, acc, 1);
        acc += __shfl_xor_sync(0xffffffffu, acc, 2);
        if (part == 0) h1[n] = __sinf(OMEGA * (acc + hb1[n]));
    }
    __syncthreads();
    {
        const float4* w = reinterpret_cast<const float4*>(hW2 + n * 256 + part * 64);
        const float4* h = reinterpret_cast<const float4*>(h1 + part * 64);
        float acc = 0.f;
#pragma unroll
        for (int i = 0; i < 16; i++) {
            float4 a = w[i], v = h[i];
            acc += a.x * v.x + a.y * v.y + a.z * v.z + a.w * v.w;
        }
        acc += __shfl_xor_sync(0xffffffffu, acc, 1);
        acc += __shfl_xor_sync(0xffffffffu, acc, 2);
        if (part == 0) g_h2[b * 256 + n] = __sinf(OMEGA * (acc + hb2[n]));
    }
}

// ---------------------------------------------------------------------------
// K2: params = h2 @ hWo^T + hbo, routed to g_small (fp32) and g_wblk (fp16,
// [n][k] with per-16-block k interleave so a B fragment is one v2 load)
// ---------------------------------------------------------------------------
__global__ void __launch_bounds__(256) hyper_out_kernel(
    const float* __restrict__ hWo, const float* __restrict__ hbo) {
    __shared__ float h2s[BATCH * 256];
    int tid = threadIdx.x;
    for (int i = tid; i < BATCH * 256; i += 256) h2s[i] = g_h2[i];
    __syncthreads();

    int j = blockIdx.x * 256 + tid;
    if (j >= P_TOTAL) return;

    float bias = hbo[j];
    float acc[BATCH];
#pragma unroll
    for (int b = 0; b < BATCH; b++) acc[b] = bias;

    const float4* w4 = reinterpret_cast<const float4*>(hWo + (size_t)j * 256);
#pragma unroll 4
    for (int c4 = 0; c4 < 64; c4++) {
        float4 w = w4[c4];
#pragma unroll
        for (int b = 0; b < BATCH; b++) {
            float4 h = *reinterpret_cast<const float4*>(&h2s[b * 256 + c4 * 4]);
            acc[b] += w.x * h.x + w.y * h.y + w.z * h.z + w.w * h.w;
        }
    }

    int layer = -1, r = 0, sidx = -1;
    if (j < 512)            sidx = j;                 // W0 + b0
    else if (j < 16896)   { layer = 0; r = j - 512; }
    else if (j < 17024)     sidx = 512 + (j - 16896); // b1
    else if (j < 33408)   { layer = 1; r = j - 17024; }
    else if (j < 33536)     sidx = 640 + (j - 33408); // b2
    else if (j < 49920)   { layer = 2; r = j - 33536; }
    else if (j < 50048)     sidx = 768 + (j - 49920); // b3
    else if (j < 50176)     sidx = 896 + (j - 50048); // Wo
    else                    sidx = 1024;              // bo

    if (layer >= 0) {
        int n = r >> 7, k = r & 127;
        int kb = k >> 4, kk = k & 15;
        // interleave within 16-block: [0,1,8,9, 2,3,10,11, 4,5,12,13, 6,7,14,15]
        int slot = ((kk & 7) >> 1) * 4 + (kk & 1) + ((kk >> 3) << 1);
        int idx = n * WS + kb * 16 + slot;
#pragma unroll
        for (int b = 0; b < BATCH; b++)
            g_wblk[b][layer * MS + idx] =
                __half_as_ushort(__float2half_rn(acc[b]));
    } else {
#pragma unroll
        for (int b = 0; b < BATCH; b++) g_small[b][sidx] = acc[b];
    }
}

// ---------------------------------------------------------------------------
// K3: warp-level fp16 MMA INR, single pass (A fp16, W fp16), 2 CTAs/SM.
// 8 warps/CTA, 16 points/warp; activations chain through registers.
// Small params read via __ldg (L1-resident broadcast), weights in SMEM.
// TILES_PER_CTA=2 -> 2048 CTAs -> ~7 waves: tail idle ~1-2% (was ~13%).
// ---------------------------------------------------------------------------
__global__ void __launch_bounds__(256, 2) inr_mma_kernel(
    const float* __restrict__ xt, float* __restrict__ out) {
    extern __shared__ char smem[];
    const uint32_t smb = smem_u32(smem);
    int tid = threadIdx.x, b = blockIdx.x;

    // weights -> SMEM (linear float4 copy)
    {
        const float4* src = reinterpret_cast<const float4*>(g_wblk[b]);
        float4* dst = reinterpret_cast<float4*>(smem);
        for (int i = tid; i < (3 * MATB) / 16; i += 256) dst[i] = src[i];
    }
    __syncthreads();

    const int lane = tid & 31, warp = tid >> 5;
    const int r = lane >> 2, q = lane & 3, qc = q * 2;
    const float* sp = g_small[b];
    // B fragment base: row n = 8j + r, k-block i, pair q
    const uint32_t wlaneoff = (uint32_t)r * (WS * 2) + (uint32_t)q * 8;

    for (int tile = 0; tile < TILES_PER_CTA; tile++) {
        int pbase = (blockIdx.y * TILES_PER_CTA + tile) * 128 + warp * 16;
        int p0 = pbase + r;
        const float* xp = xt + ((size_t)b * N_PTS + p0) * 3;
        float x0 = xp[0], y0 = xp[1], z0 = xp[2];
        float x1 = xp[24], y1 = xp[25], z1 = xp[26];  // point p0 + 8

        // ---- layer 0: build A fragments (fp16) directly in registers
        uint32_t afr[8][4];
#pragma unroll
        for (int i = 0; i < 8; i++) {
#pragma unroll
            for (int h = 0; h < 2; h++) {
                int n0 = 16 * i + 8 * h + qc;
                float wa0 = __ldg(sp + n0 * 3 + 0);
                float wa1 = __ldg(sp + n0 * 3 + 1);
                float wa2 = __ldg(sp + n0 * 3 + 2);
                float ba  = __ldg(sp + 384 + n0);
                float wb0 = __ldg(sp + n0 * 3 + 3);
                float wb1 = __ldg(sp + n0 * 3 + 4);
                float wb2 = __ldg(sp + n0 * 3 + 5);
                float bb  = __ldg(sp + 385 + n0);
                float vA0 = __sinf(OMEGA * (wa0 * x0 + wa1 * y0 + wa2 * z0 + ba));
                float vB0 = __sinf(OMEGA * (wb0 * x0 + wb1 * y0 + wb2 * z0 + bb));
                float vA1 = __sinf(OMEGA * (wa0 * x1 + wa1 * y1 + wa2 * z1 + ba));
                float vB1 = __sinf(OMEGA * (wb0 * x1 + wb1 * y1 + wb2 * z1 + bb));
                afr[i][2 * h]     = cvt2h(vA0, vB0);
                afr[i][2 * h + 1] = cvt2h(vA1, vB1);
            }
        }

        float part0 = 0.f, part1 = 0.f;
#pragma unroll 1
        for (int L = 0; L < 3; L++) {
            float acc[16][4];
#pragma unroll
            for (int j = 0; j < 16; j++) {
                acc[j][0] = 0.f; acc[j][1] = 0.f; acc[j][2] = 0.f; acc[j][3] = 0.f;
            }
            uint32_t wb_ = smb + (uint32_t)L * MATB + wlaneoff;
#pragma unroll
            for (int i = 0; i < 8; i++) {
                uint32_t koff = (uint32_t)i * 32;
#pragma unroll
                for (int jj = 0; jj < 8; jj++) {
                    uint32_t a0 = wb_ + (uint32_t)(2 * jj) * (8 * WS * 2) + koff;
                    uint32_t b00, b01, b10, b11;
                    lds64(a0, b00, b01);
                    lds64(a0 + 8 * WS * 2, b10, b11);
                    mma_fp16(acc[2 * jj],     afr[i], b00, b01);
                    mma_fp16(acc[2 * jj + 1], afr[i], b10, b11);
                }
            }

            if (L < 2) {
                // epilogue: bias + sin + fp16 cvt -> next-layer A fragments
                const float* biasp = sp + 512 + 128 * L;
#pragma unroll
                for (int j = 0; j < 16; j++) {
                    float bx = __ldg(biasp + 8 * j + qc);
                    float by = __ldg(biasp + 8 * j + qc + 1);
                    float s0 = __sinf(OMEGA * (acc[j][0] + bx));
                    float s1 = __sinf(OMEGA * (acc[j][1] + by));
                    float s2 = __sinf(OMEGA * (acc[j][2] + bx));
                    float s3 = __sinf(OMEGA * (acc[j][3] + by));
                    afr[j >> 1][(j & 1) * 2]     = cvt2h(s0, s1);
                    afr[j >> 1][(j & 1) * 2 + 1] = cvt2h(s2, s3);
                }
            } else {
                // final epilogue fused with output dot product
                const float* biasp = sp + 768;
                const float* wop   = sp + 896;
#pragma unroll
                for (int j = 0; j < 16; j++) {
                    float bx = __ldg(biasp + 8 * j + qc);
                    float by = __ldg(biasp + 8 * j + qc + 1);
                    float wx = __ldg(wop + 8 * j + qc);
                    float wy = __ldg(wop + 8 * j + qc + 1);
                    part0 += __sinf(OMEGA * (acc[j][0] + bx)) * wx
                           + __sinf(OMEGA * (acc[j][1] + by)) * wy;
                    part1 += __sinf(OMEGA * (acc[j][2] + bx)) * wx
                           + __sinf(OMEGA * (acc[j][3] + by)) * wy;
                }
            }
        }

        part0 += __shfl_xor_sync(0xffffffffu, part0, 1);
        part0 += __shfl_xor_sync(0xffffffffu, part0, 2);
        part1 += __shfl_xor_sync(0xffffffffu, part1, 1);
        part1 += __shfl_xor_sync(0xffffffffu, part1, 2);
        if ((lane & 3) == 0) {
            float bo = __ldg(sp + 1024);
            out[(size_t)b * N_PTS + p0]     = part0 + bo;
            out[(size_t)b * N_PTS + p0 + 8] = part1 + bo;
        }
    }
}

// ---------------------------------------------------------------------------
extern "C" void kernel_launch(void* const* d_in, const int* in_sizes, int n_in,
                              void* d_out, int out_size) {
    const float* t   = (const float*)d_in[0];
    const float* xt  = (const float*)d_in[1];
    const float* hW0 = (const float*)d_in[2];
    const float* hb0 = (const float*)d_in[3];
    const float* hW1 = (const float*)d_in[4];
    const float* hb1 = (const float*)d_in[5];
    const float* hW2 = (const float*)d_in[6];
    const float* hb2 = (const float*)d_in[7];
    const float* hWo = (const float*)d_in[8];
    const float* hbo = (const float*)d_in[9];
    float* out = (float*)d_out;

    hyper_hidden_kernel<<<BATCH, 1024>>>(t, hW0, hb0, hW1, hb1, hW2, hb2);
    hyper_out_kernel<<<(P_TOTAL + 255) / 256, 256>>>(hWo, hbo);

    cudaFuncSetAttribute(inr_mma_kernel,
                         cudaFuncAttributeMaxDynamicSharedMemorySize, SMEM_TOTAL);
    inr_mma_kernel<<<dim3(BATCH, CTAS_Y), 256, SMEM_TOTAL>>>(xt, out);
}

// round 13
// speedup vs baseline: 1.1107x; 1.1107x over previous
#include <cuda_runtime.h>
#include <cuda_fp16.h>
#include <cstdint>

#define OMEGA 30.0f
#define P_TOTAL 50177
#define BATCH 16
#define N_PTS 32768
#define TILES_PER_CTA 4
#define CTAS_Y 64             // 64 * 4 * 128 = 32768 points per batch

#define WS 144                // padded K stride (fp16 elems): conflict-free v2 LDS
#define MS (128 * WS)         // 18432 elems per matrix
#define MATB (MS * 2)         // 36864 bytes per matrix

// small params per batch: W0[384]@0 b0@384 b1@512 b2@640 b3@768 Wo@896 bo@1024
__device__ __align__(16) float g_h2[BATCH * 256];
__device__ __align__(16) float g_small[BATCH][1040];
// per batch: W1, W2, W3 fp16, [n][k-interleaved] with row stride WS
__device__ __align__(16) unsigned short g_wblk[BATCH][3 * MS];

#define SMEM_TOTAL (3 * MATB)              // 110592 -> 2 CTAs/SM

// ---------------------------------------------------------------------------
// helpers
// ---------------------------------------------------------------------------
__device__ __forceinline__ uint32_t smem_u32(const void* p) {
    uint32_t a;
    asm("{ .reg .u64 t; cvta.to.shared.u64 t, %1; cvt.u32.u64 %0, t; }"
        : "=r"(a) : "l"(p));
    return a;
}
__device__ __forceinline__ void lds64(uint32_t a, uint32_t& x, uint32_t& y) {
    asm volatile("ld.shared.v2.b32 {%0,%1}, [%2];" : "=r"(x), "=r"(y) : "r"(a));
}
// D += A @ B^T, m16n8k16 fp16, fp32 accum (baseline PTX, works on sm_100)
__device__ __forceinline__ void mma_fp16(float* d, const uint32_t* a,
                                         uint32_t b0, uint32_t b1) {
    asm volatile(
        "mma.sync.aligned.m16n8k16.row.col.f32.f16.f16.f32 "
        "{%0,%1,%2,%3}, {%4,%5,%6,%7}, {%8,%9}, {%0,%1,%2,%3};"
        : "+f"(d[0]), "+f"(d[1]), "+f"(d[2]), "+f"(d[3])
        : "r"(a[0]), "r"(a[1]), "r"(a[2]), "r"(a[3]), "r"(b0), "r"(b1));
}
// two fp32 -> packed fp16x2 (first value in low half)
__device__ __forceinline__ uint32_t cvt2h(float v0, float v1) {
    __half h0 = __float2half_rn(v0), h1 = __float2half_rn(v1);
    return (uint32_t)__half_as_ushort(h0) | ((uint32_t)__half_as_ushort(h1) << 16);
}

// ---------------------------------------------------------------------------
// K1: hypernet hidden chain. 1024 threads = 32 warps; each warp owns 8
// neurons, lanes span the 256-wide reduction -> every weight load is a
// 128B-contiguous warp access (4 sectors, not 64). 8 independent loads per
// neuron issue in one memory round trip; shfl tree reduces.
// ---------------------------------------------------------------------------
__global__ void __launch_bounds__(1024) hyper_hidden_kernel(
    const float* __restrict__ t,
    const float* __restrict__ hW0, const float* __restrict__ hb0,
    const float* __restrict__ hW1, const float* __restrict__ hb1,
    const float* __restrict__ hW2, const float* __restrict__ hb2) {
    __shared__ float ts[8];
    __shared__ float h0[256];
    __shared__ float h1[256];
    int b = blockIdx.x;
    int tid = threadIdx.x;
    if (tid < 8) ts[tid] = t[b * 8 + tid];
    __syncthreads();

    if (tid < 256) {
        float acc = hb0[tid];
#pragma unroll
        for (int i = 0; i < 8; i++) acc += ts[i] * hW0[tid * 8 + i];
        h0[tid] = __sinf(OMEGA * acc);
    }
    __syncthreads();

    const int warp = tid >> 5, lane = tid & 31;

    // layer 1: h1 = sin(OMEGA * (hW1 @ h0 + hb1))
    {
#pragma unroll 2
        for (int nn = 0; nn < 8; nn++) {
            int n = warp * 8 + nn;
            const float* wr = hW1 + n * 256;
            float acc = 0.f;
#pragma unroll
            for (int k = 0; k < 8; k++)
                acc += h0[lane + k * 32] * __ldg(wr + lane + k * 32);
#pragma unroll
            for (int o = 16; o > 0; o >>= 1)
                acc += __shfl_xor_sync(0xffffffffu, acc, o);
            if (lane == 0) h1[n] = __sinf(OMEGA * (acc + hb1[n]));
        }
    }
    __syncthreads();

    // layer 2: g_h2 = sin(OMEGA * (hW2 @ h1 + hb2))
    {
#pragma unroll 2
        for (int nn = 0; nn < 8; nn++) {
            int n = warp * 8 + nn;
            const float* wr = hW2 + n * 256;
            float acc = 0.f;
#pragma unroll
            for (int k = 0; k < 8; k++)
                acc += h1[lane + k * 32] * __ldg(wr + lane + k * 32);
#pragma unroll
            for (int o = 16; o > 0; o >>= 1)
                acc += __shfl_xor_sync(0xffffffffu, acc, o);
            if (lane == 0) g_h2[b * 256 + n] = __sinf(OMEGA * (acc + hb2[n]));
        }
    }
}

// ---------------------------------------------------------------------------
// K2: params = h2 @ hWo^T + hbo, routed to g_small (fp32) and g_wblk (fp16,
// [n][k] with per-16-block k interleave so a B fragment is one v2 load)
// ---------------------------------------------------------------------------
__global__ void __launch_bounds__(256) hyper_out_kernel(
    const float* __restrict__ hWo, const float* __restrict__ hbo) {
    __shared__ float h2s[BATCH * 256];
    int tid = threadIdx.x;
    for (int i = tid; i < BATCH * 256; i += 256) h2s[i] = g_h2[i];
    __syncthreads();

    int j = blockIdx.x * 256 + tid;
    if (j >= P_TOTAL) return;

    float bias = hbo[j];
    float acc[BATCH];
#pragma unroll
    for (int b = 0; b < BATCH; b++) acc[b] = bias;

    const float4* w4 = reinterpret_cast<const float4*>(hWo + (size_t)j * 256);
#pragma unroll 4
    for (int c4 = 0; c4 < 64; c4++) {
        float4 w = w4[c4];
#pragma unroll
        for (int b = 0; b < BATCH; b++) {
            float4 h = *reinterpret_cast<const float4*>(&h2s[b * 256 + c4 * 4]);
            acc[b] += w.x * h.x + w.y * h.y + w.z * h.z + w.w * h.w;
        }
    }

    int layer = -1, r = 0, sidx = -1;
    if (j < 512)            sidx = j;                 // W0 + b0
    else if (j < 16896)   { layer = 0; r = j - 512; }
    else if (j < 17024)     sidx = 512 + (j - 16896); // b1
    else if (j < 33408)   { layer = 1; r = j - 17024; }
    else if (j < 33536)     sidx = 640 + (j - 33408); // b2
    else if (j < 49920)   { layer = 2; r = j - 33536; }
    else if (j < 50048)     sidx = 768 + (j - 49920); // b3
    else if (j < 50176)     sidx = 896 + (j - 50048); // Wo
    else                    sidx = 1024;              // bo

    if (layer >= 0) {
        int n = r >> 7, k = r & 127;
        int kb = k >> 4, kk = k & 15;
        // interleave within 16-block: [0,1,8,9, 2,3,10,11, 4,5,12,13, 6,7,14,15]
        int slot = ((kk & 7) >> 1) * 4 + (kk & 1) + ((kk >> 3) << 1);
        int idx = n * WS + kb * 16 + slot;
#pragma unroll
        for (int b = 0; b < BATCH; b++)
            g_wblk[b][layer * MS + idx] =
                __half_as_ushort(__float2half_rn(acc[b]));
    } else {
#pragma unroll
        for (int b = 0; b < BATCH; b++) g_small[b][sidx] = acc[b];
    }
}

// ---------------------------------------------------------------------------
// K3: warp-level fp16 MMA INR, single pass (A fp16, W fp16), 2 CTAs/SM.
// 8 warps/CTA, 16 points/warp; activations chain through registers.
// Small params read via __ldg (L1-resident broadcast), weights in SMEM.
// ---------------------------------------------------------------------------
__global__ void __launch_bounds__(256, 2) inr_mma_kernel(
    const float* __restrict__ xt, float* __restrict__ out) {
    extern __shared__ char smem[];
    const uint32_t smb = smem_u32(smem);
    int tid = threadIdx.x, b = blockIdx.x;

    // weights -> SMEM (linear float4 copy)
    {
        const float4* src = reinterpret_cast<const float4*>(g_wblk[b]);
        float4* dst = reinterpret_cast<float4*>(smem);
        for (int i = tid; i < (3 * MATB) / 16; i += 256) dst[i] = src[i];
    }
    __syncthreads();

    const int lane = tid & 31, warp = tid >> 5;
    const int r = lane >> 2, q = lane & 3, qc = q * 2;
    const float* sp = g_small[b];
    // B fragment base: row n = 8j + r, k-block i, pair q
    const uint32_t wlaneoff = (uint32_t)r * (WS * 2) + (uint32_t)q * 8;

    for (int tile = 0; tile < TILES_PER_CTA; tile++) {
        int pbase = (blockIdx.y * TILES_PER_CTA + tile) * 128 + warp * 16;
        int p0 = pbase + r;
        const float* xp = xt + ((size_t)b * N_PTS + p0) * 3;
        float x0 = xp[0], y0 = xp[1], z0 = xp[2];
        float x1 = xp[24], y1 = xp[25], z1 = xp[26];  // point p0 + 8

        // ---- layer 0: build A fragments (fp16) directly in registers
        uint32_t afr[8][4];
#pragma unroll
        for (int i = 0; i < 8; i++) {
#pragma unroll
            for (int h = 0; h < 2; h++) {
                int n0 = 16 * i + 8 * h + qc;
                float wa0 = __ldg(sp + n0 * 3 + 0);
                float wa1 = __ldg(sp + n0 * 3 + 1);
                float wa2 = __ldg(sp + n0 * 3 + 2);
                float ba  = __ldg(sp + 384 + n0);
                float wb0 = __ldg(sp + n0 * 3 + 3);
                float wb1 = __ldg(sp + n0 * 3 + 4);
                float wb2 = __ldg(sp + n0 * 3 + 5);
                float bb  = __ldg(sp + 385 + n0);
                float vA0 = __sinf(OMEGA * (wa0 * x0 + wa1 * y0 + wa2 * z0 + ba));
                float vB0 = __sinf(OMEGA * (wb0 * x0 + wb1 * y0 + wb2 * z0 + bb));
                float vA1 = __sinf(OMEGA * (wa0 * x1 + wa1 * y1 + wa2 * z1 + ba));
                float vB1 = __sinf(OMEGA * (wb0 * x1 + wb1 * y1 + wb2 * z1 + bb));
                afr[i][2 * h]     = cvt2h(vA0, vB0);
                afr[i][2 * h + 1] = cvt2h(vA1, vB1);
            }
        }

        float part0 = 0.f, part1 = 0.f;
#pragma unroll 1
        for (int L = 0; L < 3; L++) {
            float acc[16][4];
#pragma unroll
            for (int j = 0; j < 16; j++) {
                acc[j][0] = 0.f; acc[j][1] = 0.f; acc[j][2] = 0.f; acc[j][3] = 0.f;
            }
            uint32_t wb_ = smb + (uint32_t)L * MATB + wlaneoff;
#pragma unroll
            for (int i = 0; i < 8; i++) {
                uint32_t koff = (uint32_t)i * 32;
#pragma unroll
                for (int jj = 0; jj < 8; jj++) {
                    uint32_t a0 = wb_ + (uint32_t)(2 * jj) * (8 * WS * 2) + koff;
                    uint32_t b00, b01, b10, b11;
                    lds64(a0, b00, b01);
                    lds64(a0 + 8 * WS * 2, b10, b11);
                    mma_fp16(acc[2 * jj],     afr[i], b00, b01);
                    mma_fp16(acc[2 * jj + 1], afr[i], b10, b11);
                }
            }

            if (L < 2) {
                // epilogue: bias + sin + fp16 cvt -> next-layer A fragments
                const float* biasp = sp + 512 + 128 * L;
#pragma unroll
                for (int j = 0; j < 16; j++) {
                    float bx = __ldg(biasp + 8 * j + qc);
                    float by = __ldg(biasp + 8 * j + qc + 1);
                    float s0 = __sinf(OMEGA * (acc[j][0] + bx));
                    float s1 = __sinf(OMEGA * (acc[j][1] + by));
                    float s2 = __sinf(OMEGA * (acc[j][2] + bx));
                    float s3 = __sinf(OMEGA * (acc[j][3] + by));
                    afr[j >> 1][(j & 1) * 2]     = cvt2h(s0, s1);
                    afr[j >> 1][(j & 1) * 2 + 1] = cvt2h(s2, s3);
                }
            } else {
                // final epilogue fused with output dot product
                const float* biasp = sp + 768;
                const float* wop   = sp + 896;
#pragma unroll
                for (int j = 0; j < 16; j++) {
                    float bx = __ldg(biasp + 8 * j + qc);
                    float by = __ldg(biasp + 8 * j + qc + 1);
                    float wx = __ldg(wop + 8 * j + qc);
                    float wy = __ldg(wop + 8 * j + qc + 1);
                    part0 += __sinf(OMEGA * (acc[j][0] + bx)) * wx
                           + __sinf(OMEGA * (acc[j][1] + by)) * wy;
                    part1 += __sinf(OMEGA * (acc[j][2] + bx)) * wx
                           + __sinf(OMEGA * (acc[j][3] + by)) * wy;
                }
            }
        }

        part0 += __shfl_xor_sync(0xffffffffu, part0, 1);
        part0 += __shfl_xor_sync(0xffffffffu, part0, 2);
        part1 += __shfl_xor_sync(0xffffffffu, part1, 1);
        part1 += __shfl_xor_sync(0xffffffffu, part1, 2);
        if ((lane & 3) == 0) {
            float bo = __ldg(sp + 1024);
            out[(size_t)b * N_PTS + p0]     = part0 + bo;
            out[(size_t)b * N_PTS + p0 + 8] = part1 + bo;
        }
    }
}

// ---------------------------------------------------------------------------
extern "C" void kernel_launch(void* const* d_in, const int* in_sizes, int n_in,
                              void* d_out, int out_size) {
    const float* t   = (const float*)d_in[0];
    const float* xt  = (const float*)d_in[1];
    const float* hW0 = (const float*)d_in[2];
    const float* hb0 = (const float*)d_in[3];
    const float* hW1 = (const float*)d_in[4];
    const float* hb1 = (const float*)d_in[5];
    const float* hW2 = (const float*)d_in[6];
    const float* hb2 = (const float*)d_in[7];
    const float* hWo = (const float*)d_in[8];
    const float* hbo = (const float*)d_in[9];
    float* out = (float*)d_out;

    hyper_hidden_kernel<<<BATCH, 1024>>>(t, hW0, hb0, hW1, hb1, hW2, hb2);
    hyper_out_kernel<<<(P_TOTAL + 255) / 256, 256>>>(hWo, hbo);

    cudaFuncSetAttribute(inr_mma_kernel,
                         cudaFuncAttributeMaxDynamicSharedMemorySize, SMEM_TOTAL);
    inr_mma_kernel<<<dim3(BATCH, CTAS_Y), 256, SMEM_TOTAL>>>(xt, out);
}

// round 14
// speedup vs baseline: 1.1310x; 1.0182x over previous
#include <cuda_runtime.h>
#include <cuda_fp16.h>
#include <cstdint>

#define OMEGA 30.0f
#define P_TOTAL 50177
#define BATCH 16
#define N_PTS 32768
#define TILES_PER_B 256       // 256 tiles of 128 points per batch
#define TOTAL_ITEMS (BATCH * TILES_PER_B)  // 4096

#define WS 144                // padded K stride (fp16 elems): conflict-free v2 LDS
#define MS (128 * WS)         // 18432 elems per matrix
#define MATB (MS * 2)         // 36864 bytes per matrix

// small params per batch: W0[384]@0 b0@384 b1@512 b2@640 b3@768 Wo@896 bo@1024
__device__ __align__(16) float g_h2[BATCH * 256];
__device__ __align__(16) float g_small[BATCH][1040];
// per batch: W1, W2, W3 fp16, [n][k-interleaved] with row stride WS
__device__ __align__(16) unsigned short g_wblk[BATCH][3 * MS];

#define SMEM_TOTAL (3 * MATB)              // 110592 -> 2 CTAs/SM

// ---------------------------------------------------------------------------
// helpers
// ---------------------------------------------------------------------------
__device__ __forceinline__ uint32_t smem_u32(const void* p) {
    uint32_t a;
    asm("{ .reg .u64 t; cvta.to.shared.u64 t, %1; cvt.u32.u64 %0, t; }"
        : "=r"(a) : "l"(p));
    return a;
}
__device__ __forceinline__ void lds64(uint32_t a, uint32_t& x, uint32_t& y) {
    asm volatile("ld.shared.v2.b32 {%0,%1}, [%2];" : "=r"(x), "=r"(y) : "r"(a));
}
// D += A @ B^T, m16n8k16 fp16, fp32 accum (baseline PTX, works on sm_100)
__device__ __forceinline__ void mma_fp16(float* d, const uint32_t* a,
                                         uint32_t b0, uint32_t b1) {
    asm volatile(
        "mma.sync.aligned.m16n8k16.row.col.f32.f16.f16.f32 "
        "{%0,%1,%2,%3}, {%4,%5,%6,%7}, {%8,%9}, {%0,%1,%2,%3};"
        : "+f"(d[0]), "+f"(d[1]), "+f"(d[2]), "+f"(d[3])
        : "r"(a[0]), "r"(a[1]), "r"(a[2]), "r"(a[3]), "r"(b0), "r"(b1));
}
// two fp32 -> packed fp16x2 (first value in low half)
__device__ __forceinline__ uint32_t cvt2h(float v0, float v1) {
    __half h0 = __float2half_rn(v0), h1 = __float2half_rn(v1);
    return (uint32_t)__half_as_ushort(h0) | ((uint32_t)__half_as_ushort(h1) << 16);
}

// ---------------------------------------------------------------------------
// K1: hypernet hidden chain. 32 warps; warp owns 8 neurons, lanes span the
// 256-wide reduction -> 128B-contiguous warp loads; shfl tree reduce.
// ---------------------------------------------------------------------------
__global__ void __launch_bounds__(1024) hyper_hidden_kernel(
    const float* __restrict__ t,
    const float* __restrict__ hW0, const float* __restrict__ hb0,
    const float* __restrict__ hW1, const float* __restrict__ hb1,
    const float* __restrict__ hW2, const float* __restrict__ hb2) {
    __shared__ float ts[8];
    __shared__ float h0[256];
    __shared__ float h1[256];
    int b = blockIdx.x;
    int tid = threadIdx.x;
    if (tid < 8) ts[tid] = t[b * 8 + tid];
    __syncthreads();

    if (tid < 256) {
        float acc = hb0[tid];
#pragma unroll
        for (int i = 0; i < 8; i++) acc += ts[i] * hW0[tid * 8 + i];
        h0[tid] = __sinf(OMEGA * acc);
    }
    __syncthreads();

    const int warp = tid >> 5, lane = tid & 31;

    {
#pragma unroll 2
        for (int nn = 0; nn < 8; nn++) {
            int n = warp * 8 + nn;
            const float* wr = hW1 + n * 256;
            float acc = 0.f;
#pragma unroll
            for (int k = 0; k < 8; k++)
                acc += h0[lane + k * 32] * __ldg(wr + lane + k * 32);
#pragma unroll
            for (int o = 16; o > 0; o >>= 1)
                acc += __shfl_xor_sync(0xffffffffu, acc, o);
            if (lane == 0) h1[n] = __sinf(OMEGA * (acc + hb1[n]));
        }
    }
    __syncthreads();

    {
#pragma unroll 2
        for (int nn = 0; nn < 8; nn++) {
            int n = warp * 8 + nn;
            const float* wr = hW2 + n * 256;
            float acc = 0.f;
#pragma unroll
            for (int k = 0; k < 8; k++)
                acc += h1[lane + k * 32] * __ldg(wr + lane + k * 32);
#pragma unroll
            for (int o = 16; o > 0; o >>= 1)
                acc += __shfl_xor_sync(0xffffffffu, acc, o);
            if (lane == 0) g_h2[b * 256 + n] = __sinf(OMEGA * (acc + hb2[n]));
        }
    }
}

// ---------------------------------------------------------------------------
// K2: params = h2 @ hWo^T + hbo, routed to g_small (fp32) and g_wblk (fp16,
// [n][k] with per-16-block k interleave so a B fragment is one v2 load)
// ---------------------------------------------------------------------------
__global__ void __launch_bounds__(256) hyper_out_kernel(
    const float* __restrict__ hWo, const float* __restrict__ hbo) {
    __shared__ float h2s[BATCH * 256];
    int tid = threadIdx.x;
    for (int i = tid; i < BATCH * 256; i += 256) h2s[i] = g_h2[i];
    __syncthreads();

    int j = blockIdx.x * 256 + tid;
    if (j >= P_TOTAL) return;

    float bias = hbo[j];
    float acc[BATCH];
#pragma unroll
    for (int b = 0; b < BATCH; b++) acc[b] = bias;

    const float4* w4 = reinterpret_cast<const float4*>(hWo + (size_t)j * 256);
#pragma unroll 4
    for (int c4 = 0; c4 < 64; c4++) {
        float4 w = w4[c4];
#pragma unroll
        for (int b = 0; b < BATCH; b++) {
            float4 h = *reinterpret_cast<const float4*>(&h2s[b * 256 + c4 * 4]);
            acc[b] += w.x * h.x + w.y * h.y + w.z * h.z + w.w * h.w;
        }
    }

    int layer = -1, r = 0, sidx = -1;
    if (j < 512)            sidx = j;                 // W0 + b0
    else if (j < 16896)   { layer = 0; r = j - 512; }
    else if (j < 17024)     sidx = 512 + (j - 16896); // b1
    else if (j < 33408)   { layer = 1; r = j - 17024; }
    else if (j < 33536)     sidx = 640 + (j - 33408); // b2
    else if (j < 49920)   { layer = 2; r = j - 33536; }
    else if (j < 50048)     sidx = 768 + (j - 49920); // b3
    else if (j < 50176)     sidx = 896 + (j - 50048); // Wo
    else                    sidx = 1024;              // bo

    if (layer >= 0) {
        int n = r >> 7, k = r & 127;
        int kb = k >> 4, kk = k & 15;
        // interleave within 16-block: [0,1,8,9, 2,3,10,11, 4,5,12,13, 6,7,14,15]
        int slot = ((kk & 7) >> 1) * 4 + (kk & 1) + ((kk >> 3) << 1);
        int idx = n * WS + kb * 16 + slot;
#pragma unroll
        for (int b = 0; b < BATCH; b++)
            g_wblk[b][layer * MS + idx] =
                __half_as_ushort(__float2half_rn(acc[b]));
    } else {
#pragma unroll
        for (int b = 0; b < BATCH; b++) g_small[b][sidx] = acc[b];
    }
}

// ---------------------------------------------------------------------------
// K3: persistent warp-level fp16 MMA INR, single pass (A fp16, W fp16),
// 2 CTAs/SM. Worker CTA w owns a contiguous range of the 4096 b-major tile
// items; weights reload only when b changes (~310 prologues vs 1024).
// ---------------------------------------------------------------------------
__global__ void __launch_bounds__(256, 2) inr_mma_kernel(
    const float* __restrict__ xt, float* __restrict__ out) {
    extern __shared__ char smem[];
    const uint32_t smb = smem_u32(smem);
    const int tid = threadIdx.x;
    const int W = gridDim.x, w = blockIdx.x;
    const int lo = (int)(((long long)w * TOTAL_ITEMS) / W);
    const int hi = (int)(((long long)(w + 1) * TOTAL_ITEMS) / W);

    const int lane = tid & 31, warp = tid >> 5;
    const int r = lane >> 2, q = lane & 3, qc = q * 2;
    // B fragment base: row n = 8j + r, k-block i, pair q
    const uint32_t wlaneoff = (uint32_t)r * (WS * 2) + (uint32_t)q * 8;

    int cur_b = -1;
    const float* sp = nullptr;

    for (int item = lo; item < hi; item++) {
        int b = item >> 8;          // 256 tiles per batch
        int y = item & 255;

        if (b != cur_b) {
            __syncthreads();        // all warps done with old weights
            const float4* src = reinterpret_cast<const float4*>(g_wblk[b]);
            float4* dst = reinterpret_cast<float4*>(smem);
            for (int i = tid; i < (3 * MATB) / 16; i += 256) dst[i] = src[i];
            __syncthreads();
            cur_b = b;
            sp = g_small[b];
        }

        int p0 = y * 128 + warp * 16 + r;
        const float* xp = xt + ((size_t)b * N_PTS + p0) * 3;
        float x0 = xp[0], y0 = xp[1], z0 = xp[2];
        float x1 = xp[24], y1 = xp[25], z1 = xp[26];  // point p0 + 8

        // ---- layer 0: build A fragments (fp16) directly in registers
        uint32_t afr[8][4];
#pragma unroll
        for (int i = 0; i < 8; i++) {
#pragma unroll
            for (int h = 0; h < 2; h++) {
                int n0 = 16 * i + 8 * h + qc;
                float wa0 = __ldg(sp + n0 * 3 + 0);
                float wa1 = __ldg(sp + n0 * 3 + 1);
                float wa2 = __ldg(sp + n0 * 3 + 2);
                float ba  = __ldg(sp + 384 + n0);
                float wb0 = __ldg(sp + n0 * 3 + 3);
                float wb1 = __ldg(sp + n0 * 3 + 4);
                float wb2 = __ldg(sp + n0 * 3 + 5);
                float bb  = __ldg(sp + 385 + n0);
                float vA0 = __sinf(OMEGA * (wa0 * x0 + wa1 * y0 + wa2 * z0 + ba));
                float vB0 = __sinf(OMEGA * (wb0 * x0 + wb1 * y0 + wb2 * z0 + bb));
                float vA1 = __sinf(OMEGA * (wa0 * x1 + wa1 * y1 + wa2 * z1 + ba));
                float vB1 = __sinf(OMEGA * (wb0 * x1 + wb1 * y1 + wb2 * z1 + bb));
                afr[i][2 * h]     = cvt2h(vA0, vB0);
                afr[i][2 * h + 1] = cvt2h(vA1, vB1);
            }
        }

        float part0 = 0.f, part1 = 0.f;
#pragma unroll 1
        for (int L = 0; L < 3; L++) {
            float acc[16][4];
#pragma unroll
            for (int j = 0; j < 16; j++) {
                acc[j][0] = 0.f; acc[j][1] = 0.f; acc[j][2] = 0.f; acc[j][3] = 0.f;
            }
            uint32_t wb_ = smb + (uint32_t)L * MATB + wlaneoff;
#pragma unroll
            for (int i = 0; i < 8; i++) {
                uint32_t koff = (uint32_t)i * 32;
#pragma unroll
                for (int jj = 0; jj < 8; jj++) {
                    uint32_t a0 = wb_ + (uint32_t)(2 * jj) * (8 * WS * 2) + koff;
                    uint32_t b00, b01, b10, b11;
                    lds64(a0, b00, b01);
                    lds64(a0 + 8 * WS * 2, b10, b11);
                    mma_fp16(acc[2 * jj],     afr[i], b00, b01);
                    mma_fp16(acc[2 * jj + 1], afr[i], b10, b11);
                }
            }

            if (L < 2) {
                // epilogue: bias + sin + fp16 cvt -> next-layer A fragments
                const float* biasp = sp + 512 + 128 * L;
#pragma unroll
                for (int j = 0; j < 16; j++) {
                    float bx = __ldg(biasp + 8 * j + qc);
                    float by = __ldg(biasp + 8 * j + qc + 1);
                    float s0 = __sinf(OMEGA * (acc[j][0] + bx));
                    float s1 = __sinf(OMEGA * (acc[j][1] + by));
                    float s2 = __sinf(OMEGA * (acc[j][2] + bx));
                    float s3 = __sinf(OMEGA * (acc[j][3] + by));
                    afr[j >> 1][(j & 1) * 2]     = cvt2h(s0, s1);
                    afr[j >> 1][(j & 1) * 2 + 1] = cvt2h(s2, s3);
                }
            } else {
                // final epilogue fused with output dot product
                const float* biasp = sp + 768;
                const float* wop   = sp + 896;
#pragma unroll
                for (int j = 0; j < 16; j++) {
                    float bx = __ldg(biasp + 8 * j + qc);
                    float by = __ldg(biasp + 8 * j + qc + 1);
                    float wx = __ldg(wop + 8 * j + qc);
                    float wy = __ldg(wop + 8 * j + qc + 1);
                    part0 += __sinf(OMEGA * (acc[j][0] + bx)) * wx
                           + __sinf(OMEGA * (acc[j][1] + by)) * wy;
                    part1 += __sinf(OMEGA * (acc[j][2] + bx)) * wx
                           + __sinf(OMEGA * (acc[j][3] + by)) * wy;
                }
            }
        }

        part0 += __shfl_xor_sync(0xffffffffu, part0, 1);
        part0 += __shfl_xor_sync(0xffffffffu, part0, 2);
        part1 += __shfl_xor_sync(0xffffffffu, part1, 1);
        part1 += __shfl_xor_sync(0xffffffffu, part1, 2);
        if ((lane & 3) == 0) {
            float bo = __ldg(sp + 1024);
            out[(size_t)b * N_PTS + p0]     = part0 + bo;
            out[(size_t)b * N_PTS + p0 + 8] = part1 + bo;
        }
    }
}

// ---------------------------------------------------------------------------
extern "C" void kernel_launch(void* const* d_in, const int* in_sizes, int n_in,
                              void* d_out, int out_size) {
    const float* t   = (const float*)d_in[0];
    const float* xt  = (const float*)d_in[1];
    const float* hW0 = (const float*)d_in[2];
    const float* hb0 = (const float*)d_in[3];
    const float* hW1 = (const float*)d_in[4];
    const float* hb1 = (const float*)d_in[5];
    const float* hW2 = (const float*)d_in[6];
    const float* hb2 = (const float*)d_in[7];
    const float* hWo = (const float*)d_in[8];
    const float* hbo = (const float*)d_in[9];
    float* out = (float*)d_out;

    // Host code runs at capture time only; the graph replays fixed launches.
    int sm_count = 148;
    cudaDeviceGetAttribute(&sm_count, cudaDevAttrMultiProcessorCount, 0);
    int workers = 2 * sm_count;
    if (workers > TOTAL_ITEMS) workers = TOTAL_ITEMS;

    hyper_hidden_kernel<<<BATCH, 1024>>>(t, hW0, hb0, hW1, hb1, hW2, hb2);
    hyper_out_kernel<<<(P_TOTAL + 255) / 256, 256>>>(hWo, hbo);

    cudaFuncSetAttribute(inr_mma_kernel,
                         cudaFuncAttributeMaxDynamicSharedMemorySize, SMEM_TOTAL);
    inr_mma_kernel<<<workers, 256, SMEM_TOTAL>>>(xt, out);
}

// round 15
// speedup vs baseline: 1.1864x; 1.0490x over previous
#include <cuda_runtime.h>
#include <cuda_fp16.h>
#include <cstdint>

#define OMEGA 30.0f
#define P_TOTAL 50177
#define BATCH 16
#define N_PTS 32768
#define TILES_PER_B 256       // 256 tiles of 128 points per batch
#define TOTAL_ITEMS (BATCH * TILES_PER_B)  // 4096

#define WS 144                // padded K stride (fp16 elems): conflict-free v2 LDS
#define MS (128 * WS)         // 18432 elems per matrix
#define MATB (MS * 2)         // 36864 bytes per matrix

// small params per batch (OMEGA-premultiplied where noted):
//   [0..512)   W0 packed [128]x4 = (O*w0, O*w1, O*w2, O*b0)
//   [512..640) O*b1   [640..768) O*b2   [768..896) O*b3
//   [896..1024) Wo (raw)   [1024] bo (raw)
__device__ __align__(16) float g_h2[BATCH * 256];
__device__ __align__(16) float g_small[BATCH][1040];
// per batch: W1, W2, W3 fp16, [n][k-interleaved] with row stride WS
__device__ __align__(16) unsigned short g_wblk[BATCH][3 * MS];

#define SMEM_TOTAL (3 * MATB)              // 110592 -> 2 CTAs/SM

// ---------------------------------------------------------------------------
// helpers
// ---------------------------------------------------------------------------
__device__ __forceinline__ uint32_t smem_u32(const void* p) {
    uint32_t a;
    asm("{ .reg .u64 t; cvta.to.shared.u64 t, %1; cvt.u32.u64 %0, t; }"
        : "=r"(a) : "l"(p));
    return a;
}
__device__ __forceinline__ void lds64(uint32_t a, uint32_t& x, uint32_t& y) {
    asm volatile("ld.shared.v2.b32 {%0,%1}, [%2];" : "=r"(x), "=r"(y) : "r"(a));
}
// D += A @ B^T, m16n8k16 fp16, fp32 accum (baseline PTX, works on sm_100)
__device__ __forceinline__ void mma_fp16(float* d, const uint32_t* a,
                                         uint32_t b0, uint32_t b1) {
    asm volatile(
        "mma.sync.aligned.m16n8k16.row.col.f32.f16.f16.f32 "
        "{%0,%1,%2,%3}, {%4,%5,%6,%7}, {%8,%9}, {%0,%1,%2,%3};"
        : "+f"(d[0]), "+f"(d[1]), "+f"(d[2]), "+f"(d[3])
        : "r"(a[0]), "r"(a[1]), "r"(a[2]), "r"(a[3]), "r"(b0), "r"(b1));
}
// two fp32 -> packed fp16x2 (first value in low half)
__device__ __forceinline__ uint32_t cvt2h(float v0, float v1) {
    __half h0 = __float2half_rn(v0), h1 = __float2half_rn(v1);
    return (uint32_t)__half_as_ushort(h0) | ((uint32_t)__half_as_ushort(h1) << 16);
}

// ---------------------------------------------------------------------------
// K1: hypernet hidden chain. 32 warps; warp owns 8 neurons, lanes span the
// 256-wide reduction -> 128B-contiguous warp loads; shfl tree reduce.
// ---------------------------------------------------------------------------
__global__ void __launch_bounds__(1024) hyper_hidden_kernel(
    const float* __restrict__ t,
    const float* __restrict__ hW0, const float* __restrict__ hb0,
    const float* __restrict__ hW1, const float* __restrict__ hb1,
    const float* __restrict__ hW2, const float* __restrict__ hb2) {
    __shared__ float ts[8];
    __shared__ float h0[256];
    __shared__ float h1[256];
    int b = blockIdx.x;
    int tid = threadIdx.x;
    if (tid < 8) ts[tid] = t[b * 8 + tid];
    __syncthreads();

    if (tid < 256) {
        float acc = hb0[tid];
#pragma unroll
        for (int i = 0; i < 8; i++) acc += ts[i] * hW0[tid * 8 + i];
        h0[tid] = __sinf(OMEGA * acc);
    }
    __syncthreads();

    const int warp = tid >> 5, lane = tid & 31;

    {
#pragma unroll 2
        for (int nn = 0; nn < 8; nn++) {
            int n = warp * 8 + nn;
            const float* wr = hW1 + n * 256;
            float acc = 0.f;
#pragma unroll
            for (int k = 0; k < 8; k++)
                acc += h0[lane + k * 32] * __ldg(wr + lane + k * 32);
#pragma unroll
            for (int o = 16; o > 0; o >>= 1)
                acc += __shfl_xor_sync(0xffffffffu, acc, o);
            if (lane == 0) h1[n] = __sinf(OMEGA * (acc + hb1[n]));
        }
    }
    __syncthreads();

    {
#pragma unroll 2
        for (int nn = 0; nn < 8; nn++) {
            int n = warp * 8 + nn;
            const float* wr = hW2 + n * 256;
            float acc = 0.f;
#pragma unroll
            for (int k = 0; k < 8; k++)
                acc += h1[lane + k * 32] * __ldg(wr + lane + k * 32);
#pragma unroll
            for (int o = 16; o > 0; o >>= 1)
                acc += __shfl_xor_sync(0xffffffffu, acc, o);
            if (lane == 0) g_h2[b * 256 + n] = __sinf(OMEGA * (acc + hb2[n]));
        }
    }
}

// ---------------------------------------------------------------------------
// K2: params = h2 @ hWo^T + hbo, routed to g_small (fp32, OMEGA-premultiplied
// for W0/b0/b1/b2/b3; W0 packed [n][4]) and g_wblk (fp16, MMA-ready).
// ---------------------------------------------------------------------------
__global__ void __launch_bounds__(256) hyper_out_kernel(
    const float* __restrict__ hWo, const float* __restrict__ hbo) {
    __shared__ float h2s[BATCH * 256];
    int tid = threadIdx.x;
    for (int i = tid; i < BATCH * 256; i += 256) h2s[i] = g_h2[i];
    __syncthreads();

    int j = blockIdx.x * 256 + tid;
    if (j >= P_TOTAL) return;

    float bias = hbo[j];
    float acc[BATCH];
#pragma unroll
    for (int b = 0; b < BATCH; b++) acc[b] = bias;

    const float4* w4 = reinterpret_cast<const float4*>(hWo + (size_t)j * 256);
#pragma unroll 4
    for (int c4 = 0; c4 < 64; c4++) {
        float4 w = w4[c4];
#pragma unroll
        for (int b = 0; b < BATCH; b++) {
            float4 h = *reinterpret_cast<const float4*>(&h2s[b * 256 + c4 * 4]);
            acc[b] += w.x * h.x + w.y * h.y + w.z * h.z + w.w * h.w;
        }
    }

    int layer = -1, r = 0, sidx = -1;
    float scale = 1.0f;
    if (j < 384)          { int n = j / 3, c = j - n * 3;   // W0 -> packed [n][4]
                            sidx = n * 4 + c; scale = OMEGA; }
    else if (j < 512)     { sidx = (j - 384) * 4 + 3; scale = OMEGA; }  // b0
    else if (j < 16896)   { layer = 0; r = j - 512; }
    else if (j < 17024)   { sidx = 512 + (j - 16896); scale = OMEGA; }  // b1
    else if (j < 33408)   { layer = 1; r = j - 17024; }
    else if (j < 33536)   { sidx = 640 + (j - 33408); scale = OMEGA; }  // b2
    else if (j < 49920)   { layer = 2; r = j - 33536; }
    else if (j < 50048)   { sidx = 768 + (j - 49920); scale = OMEGA; }  // b3
    else if (j < 50176)     sidx = 896 + (j - 50048); // Wo (raw)
    else                    sidx = 1024;              // bo (raw)

    if (layer >= 0) {
        int n = r >> 7, k = r & 127;
        int kb = k >> 4, kk = k & 15;
        // interleave within 16-block: [0,1,8,9, 2,3,10,11, 4,5,12,13, 6,7,14,15]
        int slot = ((kk & 7) >> 1) * 4 + (kk & 1) + ((kk >> 3) << 1);
        int idx = n * WS + kb * 16 + slot;
#pragma unroll
        for (int b = 0; b < BATCH; b++)
            g_wblk[b][layer * MS + idx] =
                __half_as_ushort(__float2half_rn(acc[b]));
    } else {
#pragma unroll
        for (int b = 0; b < BATCH; b++) g_small[b][sidx] = scale * acc[b];
    }
}

// ---------------------------------------------------------------------------
// K3: persistent warp-level fp16 MMA INR, single pass (A fp16, W fp16),
// 2 CTAs/SM. Worker CTA w owns a contiguous range of the 4096 b-major tile
// items; weights reload only when b changes. OMEGA premultiplied into
// biases -> every sin is FFMA+MUFU; layer-0 params are float4 loads.
// ---------------------------------------------------------------------------
__global__ void __launch_bounds__(256, 2) inr_mma_kernel(
    const float* __restrict__ xt, float* __restrict__ out) {
    extern __shared__ char smem[];
    const uint32_t smb = smem_u32(smem);
    const int tid = threadIdx.x;
    const int W = gridDim.x, w = blockIdx.x;
    const int lo = (int)(((long long)w * TOTAL_ITEMS) / W);
    const int hi = (int)(((long long)(w + 1) * TOTAL_ITEMS) / W);

    const int lane = tid & 31, warp = tid >> 5;
    const int r = lane >> 2, q = lane & 3, qc = q * 2;
    // B fragment base: row n = 8j + r, k-block i, pair q
    const uint32_t wlaneoff = (uint32_t)r * (WS * 2) + (uint32_t)q * 8;

    int cur_b = -1;
    const float* sp = nullptr;

    for (int item = lo; item < hi; item++) {
        int b = item >> 8;          // 256 tiles per batch
        int y = item & 255;

        if (b != cur_b) {
            __syncthreads();        // all warps done with old weights
            const float4* src = reinterpret_cast<const float4*>(g_wblk[b]);
            float4* dst = reinterpret_cast<float4*>(smem);
            for (int i = tid; i < (3 * MATB) / 16; i += 256) dst[i] = src[i];
            __syncthreads();
            cur_b = b;
            sp = g_small[b];
        }
        const float4* sp4 = reinterpret_cast<const float4*>(sp);

        int p0 = y * 128 + warp * 16 + r;
        const float* xp = xt + ((size_t)b * N_PTS + p0) * 3;
        float x0 = xp[0], y0 = xp[1], z0 = xp[2];
        float x1 = xp[24], y1 = xp[25], z1 = xp[26];  // point p0 + 8

        // ---- layer 0: packed (O*w, O*b) float4 per neuron -> A fragments
        uint32_t afr[8][4];
#pragma unroll
        for (int i = 0; i < 8; i++) {
#pragma unroll
            for (int h = 0; h < 2; h++) {
                int n0 = 16 * i + 8 * h + qc;
                float4 wA = __ldg(sp4 + n0);
                float4 wB = __ldg(sp4 + n0 + 1);
                float vA0 = __sinf(fmaf(wA.x, x0, fmaf(wA.y, y0, fmaf(wA.z, z0, wA.w))));
                float vB0 = __sinf(fmaf(wB.x, x0, fmaf(wB.y, y0, fmaf(wB.z, z0, wB.w))));
                float vA1 = __sinf(fmaf(wA.x, x1, fmaf(wA.y, y1, fmaf(wA.z, z1, wA.w))));
                float vB1 = __sinf(fmaf(wB.x, x1, fmaf(wB.y, y1, fmaf(wB.z, z1, wB.w))));
                afr[i][2 * h]     = cvt2h(vA0, vB0);
                afr[i][2 * h + 1] = cvt2h(vA1, vB1);
            }
        }

        float part0 = 0.f, part1 = 0.f;
#pragma unroll 1
        for (int L = 0; L < 3; L++) {
            float acc[16][4];
#pragma unroll
            for (int j = 0; j < 16; j++) {
                acc[j][0] = 0.f; acc[j][1] = 0.f; acc[j][2] = 0.f; acc[j][3] = 0.f;
            }
            uint32_t wb_ = smb + (uint32_t)L * MATB + wlaneoff;
#pragma unroll
            for (int i = 0; i < 8; i++) {
                uint32_t koff = (uint32_t)i * 32;
#pragma unroll
                for (int jj = 0; jj < 8; jj++) {
                    uint32_t a0 = wb_ + (uint32_t)(2 * jj) * (8 * WS * 2) + koff;
                    uint32_t b00, b01, b10, b11;
                    lds64(a0, b00, b01);
                    lds64(a0 + 8 * WS * 2, b10, b11);
                    mma_fp16(acc[2 * jj],     afr[i], b00, b01);
                    mma_fp16(acc[2 * jj + 1], afr[i], b10, b11);
                }
            }

            if (L < 2) {
                // epilogue: sin(OMEGA*acc + O*b) -> next-layer A fragments
                const float* biasp = sp + 512 + 128 * L;
#pragma unroll
                for (int j = 0; j < 16; j++) {
                    float bx = __ldg(biasp + 8 * j + qc);
                    float by = __ldg(biasp + 8 * j + qc + 1);
                    float s0 = __sinf(fmaf(OMEGA, acc[j][0], bx));
                    float s1 = __sinf(fmaf(OMEGA, acc[j][1], by));
                    float s2 = __sinf(fmaf(OMEGA, acc[j][2], bx));
                    float s3 = __sinf(fmaf(OMEGA, acc[j][3], by));
                    afr[j >> 1][(j & 1) * 2]     = cvt2h(s0, s1);
                    afr[j >> 1][(j & 1) * 2 + 1] = cvt2h(s2, s3);
                }
            } else {
                // final epilogue fused with output dot product
                const float* biasp = sp + 768;
                const float* wop   = sp + 896;
#pragma unroll
                for (int j = 0; j < 16; j++) {
                    float bx = __ldg(biasp + 8 * j + qc);
                    float by = __ldg(biasp + 8 * j + qc + 1);
                    float wx = __ldg(wop + 8 * j + qc);
                    float wy = __ldg(wop + 8 * j + qc + 1);
                    part0 += __sinf(fmaf(OMEGA, acc[j][0], bx)) * wx
                           + __sinf(fmaf(OMEGA, acc[j][1], by)) * wy;
                    part1 += __sinf(fmaf(OMEGA, acc[j][2], bx)) * wx
                           + __sinf(fmaf(OMEGA, acc[j][3], by)) * wy;
                }
            }
        }

        part0 += __shfl_xor_sync(0xffffffffu, part0, 1);
        part0 += __shfl_xor_sync(0xffffffffu, part0, 2);
        part1 += __shfl_xor_sync(0xffffffffu, part1, 1);
        part1 += __shfl_xor_sync(0xffffffffu, part1, 2);
        if ((lane & 3) == 0) {
            float bo = __ldg(sp + 1024);
            out[(size_t)b * N_PTS + p0]     = part0 + bo;
            out[(size_t)b * N_PTS + p0 + 8] = part1 + bo;
        }
    }
}

// ---------------------------------------------------------------------------
extern "C" void kernel_launch(void* const* d_in, const int* in_sizes, int n_in,
                              void* d_out, int out_size) {
    const float* t   = (const float*)d_in[0];
    const float* xt  = (const float*)d_in[1];
    const float* hW0 = (const float*)d_in[2];
    const float* hb0 = (const float*)d_in[3];
    const float* hW1 = (const float*)d_in[4];
    const float* hb1 = (const float*)d_in[5];
    const float* hW2 = (const float*)d_in[6];
    const float* hb2 = (const float*)d_in[7];
    const float* hWo = (const float*)d_in[8];
    const float* hbo = (const float*)d_in[9];
    float* out = (float*)d_out;

    // Host code runs at capture time only; the graph replays fixed launches.
    int sm_count = 148;
    cudaDeviceGetAttribute(&sm_count, cudaDevAttrMultiProcessorCount, 0);
    int workers = 2 * sm_count;
    if (workers > TOTAL_ITEMS) workers = TOTAL_ITEMS;

    hyper_hidden_kernel<<<BATCH, 1024>>>(t, hW0, hb0, hW1, hb1, hW2, hb2);
    hyper_out_kernel<<<(P_TOTAL + 255) / 256, 256>>>(hWo, hbo);

    cudaFuncSetAttribute(inr_mma_kernel,
                         cudaFuncAttributeMaxDynamicSharedMemorySize, SMEM_TOTAL);
    inr_mma_kernel<<<workers, 256, SMEM_TOTAL>>>(xt, out);
}

// round 16
// speedup vs baseline: 1.1898x; 1.0029x over previous
#include <cuda_runtime.h>
#include <cuda_fp16.h>
#include <cstdint>

#define OMEGA 30.0f
#define P_TOTAL 50177
#define BATCH 16
#define N_PTS 32768
#define ITEMS_PER_B 128       // 128 items of 256 points per batch
#define TOTAL_ITEMS (BATCH * ITEMS_PER_B)  // 2048

#define WS 144                // padded K stride (fp16 elems): conflict-free v2 LDS
#define MS (128 * WS)         // 18432 elems per matrix
#define MATB (MS * 2)         // 36864 bytes per matrix

// small params per batch (OMEGA-premultiplied where noted):
//   [0..512)   W0 packed [128]x4 = (O*w0, O*w1, O*w2, O*b0)
//   [512..640) O*b1   [640..768) O*b2   [768..896) O*b3
//   [896..1024) Wo (raw)   [1024] bo (raw)
__device__ __align__(16) float g_h2[BATCH * 256];
__device__ __align__(16) float g_small[BATCH][1040];
// per batch: W1, W2, W3 fp16, [n][k-interleaved] with row stride WS
__device__ __align__(16) unsigned short g_wblk[BATCH][3 * MS];

#define SMEM_TOTAL (3 * MATB)              // 110592

// ---------------------------------------------------------------------------
// helpers
// ---------------------------------------------------------------------------
__device__ __forceinline__ uint32_t smem_u32(const void* p) {
    uint32_t a;
    asm("{ .reg .u64 t; cvta.to.shared.u64 t, %1; cvt.u32.u64 %0, t; }"
        : "=r"(a) : "l"(p));
    return a;
}
__device__ __forceinline__ void lds64(uint32_t a, uint32_t& x, uint32_t& y) {
    asm volatile("ld.shared.v2.b32 {%0,%1}, [%2];" : "=r"(x), "=r"(y) : "r"(a));
}
// D += A @ B^T, m16n8k16 fp16, fp32 accum (baseline PTX, works on sm_100)
__device__ __forceinline__ void mma_fp16(float* d, const uint32_t* a,
                                         uint32_t b0, uint32_t b1) {
    asm volatile(
        "mma.sync.aligned.m16n8k16.row.col.f32.f16.f16.f32 "
        "{%0,%1,%2,%3}, {%4,%5,%6,%7}, {%8,%9}, {%0,%1,%2,%3};"
        : "+f"(d[0]), "+f"(d[1]), "+f"(d[2]), "+f"(d[3])
        : "r"(a[0]), "r"(a[1]), "r"(a[2]), "r"(a[3]), "r"(b0), "r"(b1));
}
// two fp32 -> packed fp16x2 (first value in low half)
__device__ __forceinline__ uint32_t cvt2h(float v0, float v1) {
    __half h0 = __float2half_rn(v0), h1 = __float2half_rn(v1);
    return (uint32_t)__half_as_ushort(h0) | ((uint32_t)__half_as_ushort(h1) << 16);
}

// ---------------------------------------------------------------------------
// K1: hypernet hidden chain. 32 warps; warp owns 8 neurons, lanes span the
// 256-wide reduction -> 128B-contiguous warp loads; shfl tree reduce.
// L2 prefetch of both weight matrices at entry hides DRAM latency.
// ---------------------------------------------------------------------------
__global__ void __launch_bounds__(1024) hyper_hidden_kernel(
    const float* __restrict__ t,
    const float* __restrict__ hW0, const float* __restrict__ hb0,
    const float* __restrict__ hW1, const float* __restrict__ hb1,
    const float* __restrict__ hW2, const float* __restrict__ hb2) {
    __shared__ float ts[8];
    __shared__ float h0[256];
    __shared__ float h1[256];
    int b = blockIdx.x;
    int tid = threadIdx.x;

    // warm L2 with hW1 + hW2 (2048 x 128B lines each) before any dependency
#pragma unroll
    for (int rep = 0; rep < 2; rep++) {
        int i = tid + rep * 1024;
        asm volatile("prefetch.global.L2 [%0];" :: "l"(hW1 + (size_t)i * 32));
        asm volatile("prefetch.global.L2 [%0];" :: "l"(hW2 + (size_t)i * 32));
    }

    if (tid < 8) ts[tid] = t[b * 8 + tid];
    __syncthreads();

    if (tid < 256) {
        float acc = hb0[tid];
#pragma unroll
        for (int i = 0; i < 8; i++) acc += ts[i] * hW0[tid * 8 + i];
        h0[tid] = __sinf(OMEGA * acc);
    }
    __syncthreads();

    const int warp = tid >> 5, lane = tid & 31;

    {
#pragma unroll 2
        for (int nn = 0; nn < 8; nn++) {
            int n = warp * 8 + nn;
            const float* wr = hW1 + n * 256;
            float acc = 0.f;
#pragma unroll
            for (int k = 0; k < 8; k++)
                acc += h0[lane + k * 32] * __ldg(wr + lane + k * 32);
#pragma unroll
            for (int o = 16; o > 0; o >>= 1)
                acc += __shfl_xor_sync(0xffffffffu, acc, o);
            if (lane == 0) h1[n] = __sinf(OMEGA * (acc + hb1[n]));
        }
    }
    __syncthreads();

    {
#pragma unroll 2
        for (int nn = 0; nn < 8; nn++) {
            int n = warp * 8 + nn;
            const float* wr = hW2 + n * 256;
            float acc = 0.f;
#pragma unroll
            for (int k = 0; k < 8; k++)
                acc += h1[lane + k * 32] * __ldg(wr + lane + k * 32);
#pragma unroll
            for (int o = 16; o > 0; o >>= 1)
                acc += __shfl_xor_sync(0xffffffffu, acc, o);
            if (lane == 0) g_h2[b * 256 + n] = __sinf(OMEGA * (acc + hb2[n]));
        }
    }
}

// ---------------------------------------------------------------------------
// K2: params = h2 @ hWo^T + hbo. 8 lanes per row j, lanes span columns ->
// coalesced 128B warp loads (4 sectors/instr, was 32). 3-level shfl reduce;
// each lane writes 2 batches. Routed to g_small (OMEGA-premult, W0 packed)
// and g_wblk (fp16, MMA-ready interleave).
// ---------------------------------------------------------------------------
__global__ void __launch_bounds__(256) hyper_out_kernel(
    const float* __restrict__ hWo, const float* __restrict__ hbo) {
    __shared__ float h2s[BATCH * 256];
    int tid = threadIdx.x;
    for (int i = tid; i < BATCH * 256; i += 256) h2s[i] = g_h2[i];
    __syncthreads();

    const int g = tid & 7;
    const int j = blockIdx.x * 32 + (tid >> 3);
    if (j >= P_TOTAL) return;

    const float4* wrow = reinterpret_cast<const float4*>(hWo + (size_t)j * 256);
    float4 w[8];
#pragma unroll
    for (int s = 0; s < 8; s++) w[s] = __ldg(wrow + s * 8 + g);

    float acc[BATCH];
#pragma unroll
    for (int b = 0; b < BATCH; b++) acc[b] = 0.f;
#pragma unroll
    for (int s = 0; s < 8; s++) {
        int c4 = s * 8 + g;
#pragma unroll
        for (int b = 0; b < BATCH; b++) {
            float4 h = *reinterpret_cast<const float4*>(&h2s[b * 256 + c4 * 4]);
            acc[b] += w[s].x * h.x + w[s].y * h.y + w[s].z * h.z + w[s].w * h.w;
        }
    }
#pragma unroll
    for (int b = 0; b < BATCH; b++) {
        acc[b] += __shfl_xor_sync(0xffffffffu, acc[b], 1);
        acc[b] += __shfl_xor_sync(0xffffffffu, acc[b], 2);
        acc[b] += __shfl_xor_sync(0xffffffffu, acc[b], 4);
    }
    float bias = __ldg(hbo + j);

    int layer = -1, r = 0, sidx = -1;
    float scale = 1.0f;
    if (j < 384)          { int n = j / 3, c = j - n * 3;   // W0 -> packed [n][4]
                            sidx = n * 4 + c; scale = OMEGA; }
    else if (j < 512)     { sidx = (j - 384) * 4 + 3; scale = OMEGA; }  // b0
    else if (j < 16896)   { layer = 0; r = j - 512; }
    else if (j < 17024)   { sidx = 512 + (j - 16896); scale = OMEGA; }  // b1
    else if (j < 33408)   { layer = 1; r = j - 17024; }
    else if (j < 33536)   { sidx = 640 + (j - 33408); scale = OMEGA; }  // b2
    else if (j < 49920)   { layer = 2; r = j - 33536; }
    else if (j < 50048)   { sidx = 768 + (j - 49920); scale = OMEGA; }  // b3
    else if (j < 50176)     sidx = 896 + (j - 50048); // Wo (raw)
    else                    sidx = 1024;              // bo (raw)

    if (layer >= 0) {
        int n = r >> 7, k = r & 127;
        int kb = k >> 4, kk = k & 15;
        // interleave within 16-block: [0,1,8,9, 2,3,10,11, 4,5,12,13, 6,7,14,15]
        int slot = ((kk & 7) >> 1) * 4 + (kk & 1) + ((kk >> 3) << 1);
        int idx = n * WS + kb * 16 + slot;
#pragma unroll
        for (int e = 0; e < 2; e++) {
            int b = g * 2 + e;
            g_wblk[b][layer * MS + idx] =
                __half_as_ushort(__float2half_rn(acc[b] + bias));
        }
    } else {
#pragma unroll
        for (int e = 0; e < 2; e++) {
            int b = g * 2 + e;
            g_small[b][sidx] = scale * (acc[b] + bias);
        }
    }
}

// ---------------------------------------------------------------------------
// K3: persistent warp-level fp16 MMA INR, single pass (A fp16, W fp16).
// One 512-thread CTA per SM (16 warps, one SMEM weight copy); item = 256
// points, all warps share the item sequence -> uniform batch-change sync.
// ---------------------------------------------------------------------------
__global__ void __launch_bounds__(512, 1) inr_mma_kernel(
    const float* __restrict__ xt, float* __restrict__ out) {
    extern __shared__ char smem[];
    const uint32_t smb = smem_u32(smem);
    const int tid = threadIdx.x;
    const int W = gridDim.x, w = blockIdx.x;
    const int lo = (int)(((long long)w * TOTAL_ITEMS) / W);
    const int hi = (int)(((long long)(w + 1) * TOTAL_ITEMS) / W);

    const int lane = tid & 31, warp = tid >> 5;   // warp 0..15
    const int r = lane >> 2, q = lane & 3, qc = q * 2;
    // B fragment base: row n = 8j + r, k-block i, pair q
    const uint32_t wlaneoff = (uint32_t)r * (WS * 2) + (uint32_t)q * 8;

    int cur_b = -1;
    const float* sp = nullptr;

    for (int item = lo; item < hi; item++) {
        int b = item >> 7;          // 128 items per batch
        int y = item & 127;

        if (b != cur_b) {
            __syncthreads();        // all warps done with old weights
            const float4* src = reinterpret_cast<const float4*>(g_wblk[b]);
            float4* dst = reinterpret_cast<float4*>(smem);
            for (int i = tid; i < (3 * MATB) / 16; i += 512) dst[i] = src[i];
            __syncthreads();
            cur_b = b;
            sp = g_small[b];
        }
        const float4* sp4 = reinterpret_cast<const float4*>(sp);

        int p0 = y * 256 + warp * 16 + r;
        const float* xp = xt + ((size_t)b * N_PTS + p0) * 3;
        float x0 = xp[0], y0 = xp[1], z0 = xp[2];
        float x1 = xp[24], y1 = xp[25], z1 = xp[26];  // point p0 + 8

        // ---- layer 0: packed (O*w, O*b) float4 per neuron -> A fragments
        uint32_t afr[8][4];
#pragma unroll
        for (int i = 0; i < 8; i++) {
#pragma unroll
            for (int h = 0; h < 2; h++) {
                int n0 = 16 * i + 8 * h + qc;
                float4 wA = __ldg(sp4 + n0);
                float4 wB = __ldg(sp4 + n0 + 1);
                float vA0 = __sinf(fmaf(wA.x, x0, fmaf(wA.y, y0, fmaf(wA.z, z0, wA.w))));
                float vB0 = __sinf(fmaf(wB.x, x0, fmaf(wB.y, y0, fmaf(wB.z, z0, wB.w))));
                float vA1 = __sinf(fmaf(wA.x, x1, fmaf(wA.y, y1, fmaf(wA.z, z1, wA.w))));
                float vB1 = __sinf(fmaf(wB.x, x1, fmaf(wB.y, y1, fmaf(wB.z, z1, wB.w))));
                afr[i][2 * h]     = cvt2h(vA0, vB0);
                afr[i][2 * h + 1] = cvt2h(vA1, vB1);
            }
        }

        float part0 = 0.f, part1 = 0.f;
#pragma unroll 1
        for (int L = 0; L < 3; L++) {
            float acc[16][4];
#pragma unroll
            for (int j = 0; j < 16; j++) {
                acc[j][0] = 0.f; acc[j][1] = 0.f; acc[j][2] = 0.f; acc[j][3] = 0.f;
            }
            uint32_t wb_ = smb + (uint32_t)L * MATB + wlaneoff;
#pragma unroll
            for (int i = 0; i < 8; i++) {
                uint32_t koff = (uint32_t)i * 32;
#pragma unroll
                for (int jj = 0; jj < 8; jj++) {
                    uint32_t a0 = wb_ + (uint32_t)(2 * jj) * (8 * WS * 2) + koff;
                    uint32_t b00, b01, b10, b11;
                    lds64(a0, b00, b01);
                    lds64(a0 + 8 * WS * 2, b10, b11);
                    mma_fp16(acc[2 * jj],     afr[i], b00, b01);
                    mma_fp16(acc[2 * jj + 1], afr[i], b10, b11);
                }
            }

            if (L < 2) {
                // epilogue: sin(OMEGA*acc + O*b) -> next-layer A fragments
                const float2* bias2 =
                    reinterpret_cast<const float2*>(sp + 512 + 128 * L);
#pragma unroll
                for (int j = 0; j < 16; j++) {
                    float2 bb = __ldg(bias2 + 4 * j + q);
                    float s0 = __sinf(fmaf(OMEGA, acc[j][0], bb.x));
                    float s1 = __sinf(fmaf(OMEGA, acc[j][1], bb.y));
                    float s2 = __sinf(fmaf(OMEGA, acc[j][2], bb.x));
                    float s3 = __sinf(fmaf(OMEGA, acc[j][3], bb.y));
                    afr[j >> 1][(j & 1) * 2]     = cvt2h(s0, s1);
                    afr[j >> 1][(j & 1) * 2 + 1] = cvt2h(s2, s3);
                }
            } else {
                // final epilogue fused with output dot product
                const float2* bias2 = reinterpret_cast<const float2*>(sp + 768);
                const float2* wo2   = reinterpret_cast<const float2*>(sp + 896);
#pragma unroll
                for (int j = 0; j < 16; j++) {
                    float2 bb = __ldg(bias2 + 4 * j + q);
                    float2 wo = __ldg(wo2 + 4 * j + q);
                    part0 += __sinf(fmaf(OMEGA, acc[j][0], bb.x)) * wo.x
                           + __sinf(fmaf(OMEGA, acc[j][1], bb.y)) * wo.y;
                    part1 += __sinf(fmaf(OMEGA, acc[j][2], bb.x)) * wo.x
                           + __sinf(fmaf(OMEGA, acc[j][3], bb.y)) * wo.y;
                }
            }
        }

        part0 += __shfl_xor_sync(0xffffffffu, part0, 1);
        part0 += __shfl_xor_sync(0xffffffffu, part0, 2);
        part1 += __shfl_xor_sync(0xffffffffu, part1, 1);
        part1 += __shfl_xor_sync(0xffffffffu, part1, 2);
        if ((lane & 3) == 0) {
            float bo = __ldg(sp + 1024);
            out[(size_t)b * N_PTS + p0]     = part0 + bo;
            out[(size_t)b * N_PTS + p0 + 8] = part1 + bo;
        }
    }
}

// ---------------------------------------------------------------------------
extern "C" void kernel_launch(void* const* d_in, const int* in_sizes, int n_in,
                              void* d_out, int out_size) {
    const float* t   = (const float*)d_in[0];
    const float* xt  = (const float*)d_in[1];
    const float* hW0 = (const float*)d_in[2];
    const float* hb0 = (const float*)d_in[3];
    const float* hW1 = (const float*)d_in[4];
    const float* hb1 = (const float*)d_in[5];
    const float* hW2 = (const float*)d_in[6];
    const float* hb2 = (const float*)d_in[7];
    const float* hWo = (const float*)d_in[8];
    const float* hbo = (const float*)d_in[9];
    float* out = (float*)d_out;

    // Host code runs at capture time only; the graph replays fixed launches.
    int sm_count = 148;
    cudaDeviceGetAttribute(&sm_count, cudaDevAttrMultiProcessorCount, 0);
    int workers = sm_count;
    if (workers > TOTAL_ITEMS) workers = TOTAL_ITEMS;

    hyper_hidden_kernel<<<BATCH, 1024>>>(t, hW0, hb0, hW1, hb1, hW2, hb2);
    hyper_out_kernel<<<(P_TOTAL + 31) / 32, 256>>>(hWo, hbo);

    cudaFuncSetAttribute(inr_mma_kernel,
                         cudaFuncAttributeMaxDynamicSharedMemorySize, SMEM_TOTAL);
    inr_mma_kernel<<<workers, 512, SMEM_TOTAL>>>(xt, out);
}

// round 17
// speedup vs baseline: 1.2133x; 1.0197x over previous
#include <cuda_runtime.h>
#include <cuda_fp16.h>
#include <cstdint>

#define OMEGA 30.0f
#define P_TOTAL 50177
#define BATCH 16
#define N_PTS 32768
#define ITEMS_PER_B 128       // 128 items of 256 points per batch
#define TOTAL_ITEMS (BATCH * ITEMS_PER_B)  // 2048

#define MS 16384              // halfs per matrix (128x128, no padding)
#define MATB (MS * 2)         // 32768 bytes per matrix

// small params per batch (OMEGA-premultiplied where noted):
//   [0..512)   W0 packed [128]x4 = (O*w0, O*w1, O*w2, O*b0)
//   [512..640) O*b1   [640..768) O*b2   [768..896) O*b3
//   [896..1024) Wo (raw)   [1024] bo (raw)
__device__ __align__(16) float g_h2[BATCH * 256];
__device__ __align__(16) float g_small[BATCH][1040];
// per batch: W1, W2, W3 fp16 in fused-pair granule layout:
// granule g16 = (jj*8+kb)*32 + r*4 + q holds rows {16jj+r, 16jj+8+r},
// k-group q of k-block kb (8B each) -> one LDS.128 feeds two MMAs.
__device__ __align__(16) unsigned short g_wblk[BATCH][3 * MS];

#define SMEM_TOTAL (3 * MATB)              // 98304

// ---------------------------------------------------------------------------
// helpers
// ---------------------------------------------------------------------------
__device__ __forceinline__ uint32_t smem_u32(const void* p) {
    uint32_t a;
    asm("{ .reg .u64 t; cvta.to.shared.u64 t, %1; cvt.u32.u64 %0, t; }"
        : "=r"(a) : "l"(p));
    return a;
}
__device__ __forceinline__ void lds128(uint32_t a, uint32_t& x, uint32_t& y,
                                       uint32_t& z, uint32_t& w) {
    asm volatile("ld.shared.v4.b32 {%0,%1,%2,%3}, [%4];"
                 : "=r"(x), "=r"(y), "=r"(z), "=r"(w) : "r"(a));
}
// D += A @ B^T, m16n8k16 fp16, fp32 accum (baseline PTX, works on sm_100)
__device__ __forceinline__ void mma_fp16(float* d, const uint32_t* a,
                                         uint32_t b0, uint32_t b1) {
    asm volatile(
        "mma.sync.aligned.m16n8k16.row.col.f32.f16.f16.f32 "
        "{%0,%1,%2,%3}, {%4,%5,%6,%7}, {%8,%9}, {%0,%1,%2,%3};"
        : "+f"(d[0]), "+f"(d[1]), "+f"(d[2]), "+f"(d[3])
        : "r"(a[0]), "r"(a[1]), "r"(a[2]), "r"(a[3]), "r"(b0), "r"(b1));
}
// two fp32 -> packed fp16x2 (first value in low half)
__device__ __forceinline__ uint32_t cvt2h(float v0, float v1) {
    __half h0 = __float2half_rn(v0), h1 = __float2half_rn(v1);
    return (uint32_t)__half_as_ushort(h0) | ((uint32_t)__half_as_ushort(h1) << 16);
}

// ---------------------------------------------------------------------------
// K1: hypernet hidden chain. 32 warps; warp owns 8 neurons, lanes span the
// 256-wide reduction -> 128B-contiguous warp loads; shfl tree reduce.
// ---------------------------------------------------------------------------
__global__ void __launch_bounds__(1024) hyper_hidden_kernel(
    const float* __restrict__ t,
    const float* __restrict__ hW0, const float* __restrict__ hb0,
    const float* __restrict__ hW1, const float* __restrict__ hb1,
    const float* __restrict__ hW2, const float* __restrict__ hb2) {
    __shared__ float ts[8];
    __shared__ float h0[256];
    __shared__ float h1[256];
    int b = blockIdx.x;
    int tid = threadIdx.x;
    if (tid < 8) ts[tid] = t[b * 8 + tid];
    __syncthreads();

    if (tid < 256) {
        float acc = hb0[tid];
#pragma unroll
        for (int i = 0; i < 8; i++) acc += ts[i] * hW0[tid * 8 + i];
        h0[tid] = __sinf(OMEGA * acc);
    }
    __syncthreads();

    const int warp = tid >> 5, lane = tid & 31;

    {
#pragma unroll 2
        for (int nn = 0; nn < 8; nn++) {
            int n = warp * 8 + nn;
            const float* wr = hW1 + n * 256;
            float acc = 0.f;
#pragma unroll
            for (int k = 0; k < 8; k++)
                acc += h0[lane + k * 32] * __ldg(wr + lane + k * 32);
#pragma unroll
            for (int o = 16; o > 0; o >>= 1)
                acc += __shfl_xor_sync(0xffffffffu, acc, o);
            if (lane == 0) h1[n] = __sinf(OMEGA * (acc + hb1[n]));
        }
    }
    __syncthreads();

    {
#pragma unroll 2
        for (int nn = 0; nn < 8; nn++) {
            int n = warp * 8 + nn;
            const float* wr = hW2 + n * 256;
            float acc = 0.f;
#pragma unroll
            for (int k = 0; k < 8; k++)
                acc += h1[lane + k * 32] * __ldg(wr + lane + k * 32);
#pragma unroll
            for (int o = 16; o > 0; o >>= 1)
                acc += __shfl_xor_sync(0xffffffffu, acc, o);
            if (lane == 0) g_h2[b * 256 + n] = __sinf(OMEGA * (acc + hb2[n]));
        }
    }
}

// ---------------------------------------------------------------------------
// K2: params = h2 @ hWo^T + hbo. 8 lanes per row j, lanes span columns ->
// coalesced 128B warp loads; 3-level shfl reduce; each lane writes 2 batches.
// Routes to g_small (OMEGA-premult, W0 packed) and g_wblk (fp16, fused-pair
// granule layout for single-LDS.128 B fragments).
// ---------------------------------------------------------------------------
__global__ void __launch_bounds__(256) hyper_out_kernel(
    const float* __restrict__ hWo, const float* __restrict__ hbo) {
    __shared__ float h2s[BATCH * 256];
    int tid = threadIdx.x;
    for (int i = tid; i < BATCH * 256; i += 256) h2s[i] = g_h2[i];
    __syncthreads();

    const int g = tid & 7;
    const int j = blockIdx.x * 32 + (tid >> 3);
    if (j >= P_TOTAL) return;

    const float4* wrow = reinterpret_cast<const float4*>(hWo + (size_t)j * 256);
    float4 w[8];
#pragma unroll
    for (int s = 0; s < 8; s++) w[s] = __ldg(wrow + s * 8 + g);

    float acc[BATCH];
#pragma unroll
    for (int b = 0; b < BATCH; b++) acc[b] = 0.f;
#pragma unroll
    for (int s = 0; s < 8; s++) {
        int c4 = s * 8 + g;
#pragma unroll
        for (int b = 0; b < BATCH; b++) {
            float4 h = *reinterpret_cast<const float4*>(&h2s[b * 256 + c4 * 4]);
            acc[b] += w[s].x * h.x + w[s].y * h.y + w[s].z * h.z + w[s].w * h.w;
        }
    }
#pragma unroll
    for (int b = 0; b < BATCH; b++) {
        acc[b] += __shfl_xor_sync(0xffffffffu, acc[b], 1);
        acc[b] += __shfl_xor_sync(0xffffffffu, acc[b], 2);
        acc[b] += __shfl_xor_sync(0xffffffffu, acc[b], 4);
    }
    float bias = __ldg(hbo + j);

    int layer = -1, r = 0, sidx = -1;
    float scale = 1.0f;
    if (j < 384)          { int n = j / 3, c = j - n * 3;   // W0 -> packed [n][4]
                            sidx = n * 4 + c; scale = OMEGA; }
    else if (j < 512)     { sidx = (j - 384) * 4 + 3; scale = OMEGA; }  // b0
    else if (j < 16896)   { layer = 0; r = j - 512; }
    else if (j < 17024)   { sidx = 512 + (j - 16896); scale = OMEGA; }  // b1
    else if (j < 33408)   { layer = 1; r = j - 17024; }
    else if (j < 33536)   { sidx = 640 + (j - 33408); scale = OMEGA; }  // b2
    else if (j < 49920)   { layer = 2; r = j - 33536; }
    else if (j < 50048)   { sidx = 768 + (j - 49920); scale = OMEGA; }  // b3
    else if (j < 50176)     sidx = 896 + (j - 50048); // Wo (raw)
    else                    sidx = 1024;              // bo (raw)

    if (layer >= 0) {
        int n = r >> 7, k = r & 127;
        int rr = n & 7, hb = (n >> 3) & 1, jj = n >> 4;
        int kb = k >> 4, kk = k & 15;
        // k interleave within 16-block: group q holds kk = {2q,2q+1,2q+8,2q+9}
        int slot = ((kk & 7) >> 1) * 4 + (kk & 1) + ((kk >> 3) << 1);
        int qq = slot >> 2, pos = slot & 3;
        int idx = (((jj * 8 + kb) * 32 + rr * 4 + qq) << 3) + hb * 4 + pos;
#pragma unroll
        for (int e = 0; e < 2; e++) {
            int b = g * 2 + e;
            g_wblk[b][layer * MS + idx] =
                __half_as_ushort(__float2half_rn(acc[b] + bias));
        }
    } else {
#pragma unroll
        for (int e = 0; e < 2; e++) {
            int b = g * 2 + e;
            g_small[b][sidx] = scale * (acc[b] + bias);
        }
    }
}

// ---------------------------------------------------------------------------
// K3: persistent warp-level fp16 MMA INR, single pass (A fp16, W fp16).
// One 512-thread CTA per SM; item = 256 points. Fused-pair weight granules:
// one LDS.128 per (i,jj) feeds both MMAs; warp addresses linear (no
// conflicts), no padding, one IMAD of address math per step.
// ---------------------------------------------------------------------------
__global__ void __launch_bounds__(512, 1) inr_mma_kernel(
    const float* __restrict__ xt, float* __restrict__ out) {
    extern __shared__ char smem[];
    const uint32_t smb = smem_u32(smem);
    const int tid = threadIdx.x;
    const int W = gridDim.x, w = blockIdx.x;
    const int lo = (int)(((long long)w * TOTAL_ITEMS) / W);
    const int hi = (int)(((long long)(w + 1) * TOTAL_ITEMS) / W);

    const int lane = tid & 31, warp = tid >> 5;   // warp 0..15
    const int r = lane >> 2, q = lane & 3, qc = q * 2;
    const uint32_t laneoff = (uint32_t)lane * 16;  // granule = lane*16 bytes

    int cur_b = -1;
    const float* sp = nullptr;

    for (int item = lo; item < hi; item++) {
        int b = item >> 7;          // 128 items per batch
        int y = item & 127;

        if (b != cur_b) {
            __syncthreads();        // all warps done with old weights
            const float4* src = reinterpret_cast<const float4*>(g_wblk[b]);
            float4* dst = reinterpret_cast<float4*>(smem);
            for (int i = tid; i < (3 * MATB) / 16; i += 512) dst[i] = src[i];
            __syncthreads();
            cur_b = b;
            sp = g_small[b];
        }
        const float4* sp4 = reinterpret_cast<const float4*>(sp);

        int p0 = y * 256 + warp * 16 + r;
        const float* xp = xt + ((size_t)b * N_PTS + p0) * 3;
        float x0 = xp[0], y0 = xp[1], z0 = xp[2];
        float x1 = xp[24], y1 = xp[25], z1 = xp[26];  // point p0 + 8

        // ---- layer 0: packed (O*w, O*b) float4 per neuron -> A fragments
        uint32_t afr[8][4];
#pragma unroll
        for (int i = 0; i < 8; i++) {
#pragma unroll
            for (int h = 0; h < 2; h++) {
                int n0 = 16 * i + 8 * h + qc;
                float4 wA = __ldg(sp4 + n0);
                float4 wB = __ldg(sp4 + n0 + 1);
                float vA0 = __sinf(fmaf(wA.x, x0, fmaf(wA.y, y0, fmaf(wA.z, z0, wA.w))));
                float vB0 = __sinf(fmaf(wB.x, x0, fmaf(wB.y, y0, fmaf(wB.z, z0, wB.w))));
                float vA1 = __sinf(fmaf(wA.x, x1, fmaf(wA.y, y1, fmaf(wA.z, z1, wA.w))));
                float vB1 = __sinf(fmaf(wB.x, x1, fmaf(wB.y, y1, fmaf(wB.z, z1, wB.w))));
                afr[i][2 * h]     = cvt2h(vA0, vB0);
                afr[i][2 * h + 1] = cvt2h(vA1, vB1);
            }
        }

        float part0 = 0.f, part1 = 0.f;
#pragma unroll 1
        for (int L = 0; L < 3; L++) {
            float acc[16][4];
#pragma unroll
            for (int j = 0; j < 16; j++) {
                acc[j][0] = 0.f; acc[j][1] = 0.f; acc[j][2] = 0.f; acc[j][3] = 0.f;
            }
            uint32_t base_ = smb + (uint32_t)L * MATB + laneoff;
#pragma unroll
            for (int i = 0; i < 8; i++) {
#pragma unroll
                for (int jj = 0; jj < 8; jj++) {
                    uint32_t a0 = base_ + (uint32_t)(jj * 4096 + i * 512);
                    uint32_t w0, w1, w2, w3;
                    lds128(a0, w0, w1, w2, w3);
                    mma_fp16(acc[2 * jj],     afr[i], w0, w1);
                    mma_fp16(acc[2 * jj + 1], afr[i], w2, w3);
                }
            }

            if (L < 2) {
                // epilogue: sin(OMEGA*acc + O*b) -> next-layer A fragments
                const float2* bias2 =
                    reinterpret_cast<const float2*>(sp + 512 + 128 * L);
#pragma unroll
                for (int j = 0; j < 16; j++) {
                    float2 bb = __ldg(bias2 + 4 * j + q);
                    float s0 = __sinf(fmaf(OMEGA, acc[j][0], bb.x));
                    float s1 = __sinf(fmaf(OMEGA, acc[j][1], bb.y));
                    float s2 = __sinf(fmaf(OMEGA, acc[j][2], bb.x));
                    float s3 = __sinf(fmaf(OMEGA, acc[j][3], bb.y));
                    afr[j >> 1][(j & 1) * 2]     = cvt2h(s0, s1);
                    afr[j >> 1][(j & 1) * 2 + 1] = cvt2h(s2, s3);
                }
            } else {
                // final epilogue fused with output dot product
                const float2* bias2 = reinterpret_cast<const float2*>(sp + 768);
                const float2* wo2   = reinterpret_cast<const float2*>(sp + 896);
#pragma unroll
                for (int j = 0; j < 16; j++) {
                    float2 bb = __ldg(bias2 + 4 * j + q);
                    float2 wo = __ldg(wo2 + 4 * j + q);
                    part0 += __sinf(fmaf(OMEGA, acc[j][0], bb.x)) * wo.x
                           + __sinf(fmaf(OMEGA, acc[j][1], bb.y)) * wo.y;
                    part1 += __sinf(fmaf(OMEGA, acc[j][2], bb.x)) * wo.x
                           + __sinf(fmaf(OMEGA, acc[j][3], bb.y)) * wo.y;
                }
            }
        }

        part0 += __shfl_xor_sync(0xffffffffu, part0, 1);
        part0 += __shfl_xor_sync(0xffffffffu, part0, 2);
        part1 += __shfl_xor_sync(0xffffffffu, part1, 1);
        part1 += __shfl_xor_sync(0xffffffffu, part1, 2);
        if ((lane & 3) == 0) {
            float bo = __ldg(sp + 1024);
            out[(size_t)b * N_PTS + p0]     = part0 + bo;
            out[(size_t)b * N_PTS + p0 + 8] = part1 + bo;
        }
    }
}

// ---------------------------------------------------------------------------
extern "C" void kernel_launch(void* const* d_in, const int* in_sizes, int n_in,
                              void* d_out, int out_size) {
    const float* t   = (const float*)d_in[0];
    const float* xt  = (const float*)d_in[1];
    const float* hW0 = (const float*)d_in[2];
    const float* hb0 = (const float*)d_in[3];
    const float* hW1 = (const float*)d_in[4];
    const float* hb1 = (const float*)d_in[5];
    const float* hW2 = (const float*)d_in[6];
    const float* hb2 = (const float*)d_in[7];
    const float* hWo = (const float*)d_in[8];
    const float* hbo = (const float*)d_in[9];
    float* out = (float*)d_out;

    // Host code runs at capture time only; the graph replays fixed launches.
    int sm_count = 148;
    cudaDeviceGetAttribute(&sm_count, cudaDevAttrMultiProcessorCount, 0);
    int workers = sm_count;
    if (workers > TOTAL_ITEMS) workers = TOTAL_ITEMS;

    hyper_hidden_kernel<<<BATCH, 1024>>>(t, hW0, hb0, hW1, hb1, hW2, hb2);
    hyper_out_kernel<<<(P_TOTAL + 31) / 32, 256>>>(hWo, hbo);

    cudaFuncSetAttribute(inr_mma_kernel,
                         cudaFuncAttributeMaxDynamicSharedMemorySize, SMEM_TOTAL);
    inr_mma_kernel<<<workers, 512, SMEM_TOTAL>>>(xt, out);
}